// round 1
// baseline (speedup 1.0000x reference)
#include <cuda_runtime.h>

// Problem constants
constexpr int Bb = 2;
constexpr int Tt = 2048;
constexpr int Dd = 2048;
constexpr int Nh = 16;
constexpr int Hd = 128;
constexpr int Ss = Tt;
constexpr float QSCALE = 0.08838834764831845f; // 1/sqrt(128)

// Scratch (device globals — no allocation allowed)
__device__ float g_q[(size_t)Bb * Tt * Dd];
__device__ float g_k[(size_t)Bb * Tt * Dd];
__device__ float g_v[(size_t)Bb * Tt * Dd];
__device__ float g_ctx[(size_t)Bb * Tt * Dd];
__device__ float g_m[(size_t)Bb * Nh * Tt];
__device__ float g_l[(size_t)Bb * Nh * Tt];

// ---------------------------------------------------------------------------
// Kernel 1: fused QKV projection.  C = X @ W (+bias)(*scale)
// X [4096, 2048] row-major, W [2048, 2048] row-major (d-major, nh inner).
// blockIdx.z selects q/k/v.  128x128 tile, BK=16, 256 threads, 8x8 per thread.
// ---------------------------------------------------------------------------
__global__ __launch_bounds__(256, 2)
void proj_kernel(const float* __restrict__ X,
                 const float* __restrict__ Wq, const float* __restrict__ Wk,
                 const float* __restrict__ Wv,
                 const float* __restrict__ bq, const float* __restrict__ bk,
                 const float* __restrict__ bv)
{
    const int z = blockIdx.z;
    const float* __restrict__ W    = (z == 0) ? Wq : (z == 1) ? Wk : Wv;
    const float* __restrict__ bias = (z == 0) ? bq : (z == 1) ? bk : bv;
    float* __restrict__ Out        = (z == 0) ? g_q : (z == 1) ? g_k : g_v;
    const float scale = (z == 0) ? QSCALE : 1.0f;

    __shared__ float As[16][128];
    __shared__ float Bs[16][128];

    const int tid = threadIdx.x;
    const int tx = tid & 15;
    const int ty = tid >> 4;
    const int m0 = blockIdx.y * 128;
    const int n0 = blockIdx.x * 128;

    const int arow = tid >> 2;          // 0..63
    const int acol = (tid & 3) << 2;    // 0,4,8,12
    const int brow = tid >> 5;          // 0..7
    const int bcol = (tid & 31) << 2;   // 0..124

    float acc[8][8];
#pragma unroll
    for (int i = 0; i < 8; i++)
#pragma unroll
        for (int j = 0; j < 8; j++) acc[i][j] = 0.f;

    for (int k0 = 0; k0 < Dd; k0 += 16) {
        float4 a0 = *reinterpret_cast<const float4*>(X + (size_t)(m0 + arow) * Dd + k0 + acol);
        float4 a1 = *reinterpret_cast<const float4*>(X + (size_t)(m0 + arow + 64) * Dd + k0 + acol);
        float4 b0 = *reinterpret_cast<const float4*>(W + (size_t)(k0 + brow) * Dd + n0 + bcol);
        float4 b1 = *reinterpret_cast<const float4*>(W + (size_t)(k0 + brow + 8) * Dd + n0 + bcol);
        __syncthreads();
        As[acol + 0][arow] = a0.x; As[acol + 1][arow] = a0.y;
        As[acol + 2][arow] = a0.z; As[acol + 3][arow] = a0.w;
        As[acol + 0][arow + 64] = a1.x; As[acol + 1][arow + 64] = a1.y;
        As[acol + 2][arow + 64] = a1.z; As[acol + 3][arow + 64] = a1.w;
        *reinterpret_cast<float4*>(&Bs[brow][bcol]) = b0;
        *reinterpret_cast<float4*>(&Bs[brow + 8][bcol]) = b1;
        __syncthreads();
#pragma unroll
        for (int k = 0; k < 16; k++) {
            float ra[8], rb[8];
#pragma unroll
            for (int i = 0; i < 8; i++) ra[i] = As[k][ty * 8 + i];
#pragma unroll
            for (int j = 0; j < 8; j++) rb[j] = Bs[k][tx * 8 + j];
#pragma unroll
            for (int i = 0; i < 8; i++)
#pragma unroll
                for (int j = 0; j < 8; j++) acc[i][j] += ra[i] * rb[j];
        }
    }

    float4 bb0 = *reinterpret_cast<const float4*>(bias + n0 + tx * 8);
    float4 bb1 = *reinterpret_cast<const float4*>(bias + n0 + tx * 8 + 4);
#pragma unroll
    for (int i = 0; i < 8; i++) {
        const int row = m0 + ty * 8 + i;
        float4 o0 = make_float4((acc[i][0] + bb0.x) * scale, (acc[i][1] + bb0.y) * scale,
                                (acc[i][2] + bb0.z) * scale, (acc[i][3] + bb0.w) * scale);
        float4 o1 = make_float4((acc[i][4] + bb1.x) * scale, (acc[i][5] + bb1.y) * scale,
                                (acc[i][6] + bb1.z) * scale, (acc[i][7] + bb1.w) * scale);
        *reinterpret_cast<float4*>(Out + (size_t)row * Dd + n0 + tx * 8) = o0;
        *reinterpret_cast<float4*>(Out + (size_t)row * Dd + n0 + tx * 8 + 4) = o1;
    }
}

// ---------------------------------------------------------------------------
// Kernel 2: logits = Q_bn @ K_bn^T + bias (raw, written to probs region),
// plus online per-row (max, sumexp) stats -> g_m, g_l.
// Per block: one (b,n) head, 128 t-rows, all 2048 s-cols.
// ---------------------------------------------------------------------------
__global__ __launch_bounds__(256, 2)
void logits_stats_kernel(const float* __restrict__ biasTS, float* __restrict__ probs)
{
    const int bn = blockIdx.y;
    const int b = bn >> 4;
    const int n = bn & 15;
    const int t0 = blockIdx.x * 128;

    const float* __restrict__ Qp = g_q + (size_t)b * Tt * Dd + n * Hd;
    const float* __restrict__ Kp = g_k + (size_t)b * Tt * Dd + n * Hd;
    float* __restrict__ Lout = probs + (size_t)bn * Tt * Ss;

    __shared__ float As[16][128];
    __shared__ float Bs[16][128];
    __shared__ float red_m[128][16];
    __shared__ float red_s[128][16];

    const int tid = threadIdx.x;
    const int tx = tid & 15;
    const int ty = tid >> 4;
    const int arow = tid >> 2;
    const int acol = (tid & 3) << 2;

    float m_loc[8], s_loc[8];
#pragma unroll
    for (int i = 0; i < 8; i++) { m_loc[i] = -1e30f; s_loc[i] = 0.f; }

    for (int st = 0; st < 16; st++) {
        const int s0 = st * 128;
        float acc[8][8];
#pragma unroll
        for (int i = 0; i < 8; i++)
#pragma unroll
            for (int j = 0; j < 8; j++) acc[i][j] = 0.f;

        for (int k0 = 0; k0 < Hd; k0 += 16) {
            float4 a0 = *reinterpret_cast<const float4*>(Qp + (size_t)(t0 + arow) * Dd + k0 + acol);
            float4 a1 = *reinterpret_cast<const float4*>(Qp + (size_t)(t0 + arow + 64) * Dd + k0 + acol);
            float4 b0 = *reinterpret_cast<const float4*>(Kp + (size_t)(s0 + arow) * Dd + k0 + acol);
            float4 b1 = *reinterpret_cast<const float4*>(Kp + (size_t)(s0 + arow + 64) * Dd + k0 + acol);
            __syncthreads();
            As[acol + 0][arow] = a0.x; As[acol + 1][arow] = a0.y;
            As[acol + 2][arow] = a0.z; As[acol + 3][arow] = a0.w;
            As[acol + 0][arow + 64] = a1.x; As[acol + 1][arow + 64] = a1.y;
            As[acol + 2][arow + 64] = a1.z; As[acol + 3][arow + 64] = a1.w;
            Bs[acol + 0][arow] = b0.x; Bs[acol + 1][arow] = b0.y;
            Bs[acol + 2][arow] = b0.z; Bs[acol + 3][arow] = b0.w;
            Bs[acol + 0][arow + 64] = b1.x; Bs[acol + 1][arow + 64] = b1.y;
            Bs[acol + 2][arow + 64] = b1.z; Bs[acol + 3][arow + 64] = b1.w;
            __syncthreads();
#pragma unroll
            for (int k = 0; k < 16; k++) {
                float ra[8], rb[8];
#pragma unroll
                for (int i = 0; i < 8; i++) ra[i] = As[k][ty * 8 + i];
#pragma unroll
                for (int j = 0; j < 8; j++) rb[j] = Bs[k][tx * 8 + j];
#pragma unroll
                for (int i = 0; i < 8; i++)
#pragma unroll
                    for (int j = 0; j < 8; j++) acc[i][j] += ra[i] * rb[j];
            }
        }

        // bias add, online stats, raw-logit store
#pragma unroll
        for (int i = 0; i < 8; i++) {
            const int row = t0 + ty * 8 + i;
            const float* bp = biasTS + (size_t)row * Ss + s0 + tx * 8;
            float4 c0 = *reinterpret_cast<const float4*>(bp);
            float4 c1 = *reinterpret_cast<const float4*>(bp + 4);
            float l[8];
            l[0] = acc[i][0] + c0.x; l[1] = acc[i][1] + c0.y;
            l[2] = acc[i][2] + c0.z; l[3] = acc[i][3] + c0.w;
            l[4] = acc[i][4] + c1.x; l[5] = acc[i][5] + c1.y;
            l[6] = acc[i][6] + c1.z; l[7] = acc[i][7] + c1.w;
            float tm = l[0];
#pragma unroll
            for (int j = 1; j < 8; j++) tm = fmaxf(tm, l[j]);
            float m_new = fmaxf(m_loc[i], tm);
            float corr = __expf(m_loc[i] - m_new);
            float add = 0.f;
#pragma unroll
            for (int j = 0; j < 8; j++) add += __expf(l[j] - m_new);
            s_loc[i] = s_loc[i] * corr + add;
            m_loc[i] = m_new;
            float4 o0 = make_float4(l[0], l[1], l[2], l[3]);
            float4 o1 = make_float4(l[4], l[5], l[6], l[7]);
            *reinterpret_cast<float4*>(Lout + (size_t)row * Ss + s0 + tx * 8) = o0;
            *reinterpret_cast<float4*>(Lout + (size_t)row * Ss + s0 + tx * 8 + 4) = o1;
        }
    }

    // cross-thread (tx) merge of per-row stats
#pragma unroll
    for (int i = 0; i < 8; i++) {
        red_m[ty * 8 + i][tx] = m_loc[i];
        red_s[ty * 8 + i][tx] = s_loc[i];
    }
    __syncthreads();
    if (tid < 128) {
        float m = -1e30f;
#pragma unroll
        for (int x = 0; x < 16; x++) m = fmaxf(m, red_m[tid][x]);
        float s = 0.f;
#pragma unroll
        for (int x = 0; x < 16; x++) s += red_s[tid][x] * __expf(red_m[tid][x] - m);
        g_m[(size_t)bn * Tt + t0 + tid] = m;
        g_l[(size_t)bn * Tt + t0 + tid] = s;
    }
}

// ---------------------------------------------------------------------------
// Kernel 3: in-place softmax on probs + fused PV -> g_ctx (btnh layout).
// ctx[t, h] = sum_s P[t, s] * V[s, h]   (M=128 t, N=128 h, K=2048 s, BK=16)
// ---------------------------------------------------------------------------
__global__ __launch_bounds__(256, 2)
void softmax_pv_kernel(float* __restrict__ probs)
{
    const int bn = blockIdx.y;
    const int b = bn >> 4;
    const int n = bn & 15;
    const int t0 = blockIdx.x * 128;

    const float* __restrict__ Vp = g_v + (size_t)b * Tt * Dd + n * Hd;
    float* __restrict__ Lp = probs + (size_t)bn * Tt * Ss;

    __shared__ float As[16][128];
    __shared__ float Bs[16][128];
    __shared__ float sm_m[128];
    __shared__ float sm_inv[128];

    const int tid = threadIdx.x;
    const int tx = tid & 15;
    const int ty = tid >> 4;
    const int arow = tid >> 2;          // 0..63 (t rows)
    const int acol = (tid & 3) << 2;    // s offset in chunk
    const int vrow = tid >> 5;          // 0..7 (s rows)
    const int vcol = (tid & 31) << 2;   // h

    if (tid < 128) {
        sm_m[tid] = g_m[(size_t)bn * Tt + t0 + tid];
        sm_inv[tid] = 1.0f / g_l[(size_t)bn * Tt + t0 + tid];
    }
    __syncthreads();

    float acc[8][8];
#pragma unroll
    for (int i = 0; i < 8; i++)
#pragma unroll
        for (int j = 0; j < 8; j++) acc[i][j] = 0.f;

    for (int s0 = 0; s0 < Ss; s0 += 16) {
        float4 a0 = *reinterpret_cast<const float4*>(Lp + (size_t)(t0 + arow) * Ss + s0 + acol);
        float4 a1 = *reinterpret_cast<const float4*>(Lp + (size_t)(t0 + arow + 64) * Ss + s0 + acol);
        const float m0v = sm_m[arow],      i0v = sm_inv[arow];
        const float m1v = sm_m[arow + 64], i1v = sm_inv[arow + 64];
        a0.x = __expf(a0.x - m0v) * i0v; a0.y = __expf(a0.y - m0v) * i0v;
        a0.z = __expf(a0.z - m0v) * i0v; a0.w = __expf(a0.w - m0v) * i0v;
        a1.x = __expf(a1.x - m1v) * i1v; a1.y = __expf(a1.y - m1v) * i1v;
        a1.z = __expf(a1.z - m1v) * i1v; a1.w = __expf(a1.w - m1v) * i1v;
        *reinterpret_cast<float4*>(Lp + (size_t)(t0 + arow) * Ss + s0 + acol) = a0;
        *reinterpret_cast<float4*>(Lp + (size_t)(t0 + arow + 64) * Ss + s0 + acol) = a1;

        float4 v0 = *reinterpret_cast<const float4*>(Vp + (size_t)(s0 + vrow) * Dd + vcol);
        float4 v1 = *reinterpret_cast<const float4*>(Vp + (size_t)(s0 + vrow + 8) * Dd + vcol);
        __syncthreads();
        As[acol + 0][arow] = a0.x; As[acol + 1][arow] = a0.y;
        As[acol + 2][arow] = a0.z; As[acol + 3][arow] = a0.w;
        As[acol + 0][arow + 64] = a1.x; As[acol + 1][arow + 64] = a1.y;
        As[acol + 2][arow + 64] = a1.z; As[acol + 3][arow + 64] = a1.w;
        *reinterpret_cast<float4*>(&Bs[vrow][vcol]) = v0;
        *reinterpret_cast<float4*>(&Bs[vrow + 8][vcol]) = v1;
        __syncthreads();
#pragma unroll
        for (int k = 0; k < 16; k++) {
            float ra[8], rb[8];
#pragma unroll
            for (int i = 0; i < 8; i++) ra[i] = As[k][ty * 8 + i];
#pragma unroll
            for (int j = 0; j < 8; j++) rb[j] = Bs[k][tx * 8 + j];
#pragma unroll
            for (int i = 0; i < 8; i++)
#pragma unroll
                for (int j = 0; j < 8; j++) acc[i][j] += ra[i] * rb[j];
        }
    }

#pragma unroll
    for (int i = 0; i < 8; i++) {
        const int row = t0 + ty * 8 + i;
        float* cp = g_ctx + (size_t)(b * Tt + row) * Dd + n * Hd + tx * 8;
        *reinterpret_cast<float4*>(cp)     = make_float4(acc[i][0], acc[i][1], acc[i][2], acc[i][3]);
        *reinterpret_cast<float4*>(cp + 4) = make_float4(acc[i][4], acc[i][5], acc[i][6], acc[i][7]);
    }
}

// ---------------------------------------------------------------------------
// Kernel 4: output projection (NT GEMM): data[bt, d] = ctx[bt, :] . Wo[d, :] + ob[d]
// ---------------------------------------------------------------------------
__global__ __launch_bounds__(256, 2)
void oproj_kernel(const float* __restrict__ Wo, const float* __restrict__ ob,
                  float* __restrict__ out)
{
    __shared__ float As[16][128];
    __shared__ float Bs[16][128];

    const int tid = threadIdx.x;
    const int tx = tid & 15;
    const int ty = tid >> 4;
    const int m0 = blockIdx.y * 128;
    const int n0 = blockIdx.x * 128;

    const int arow = tid >> 2;
    const int acol = (tid & 3) << 2;

    float acc[8][8];
#pragma unroll
    for (int i = 0; i < 8; i++)
#pragma unroll
        for (int j = 0; j < 8; j++) acc[i][j] = 0.f;

    for (int k0 = 0; k0 < Dd; k0 += 16) {
        float4 a0 = *reinterpret_cast<const float4*>(g_ctx + (size_t)(m0 + arow) * Dd + k0 + acol);
        float4 a1 = *reinterpret_cast<const float4*>(g_ctx + (size_t)(m0 + arow + 64) * Dd + k0 + acol);
        // Wo tile: rows n (128), cols k (16) -> transpose to Bs[k][n]
        float4 w0 = *reinterpret_cast<const float4*>(Wo + (size_t)(n0 + arow) * Dd + k0 + acol);
        float4 w1 = *reinterpret_cast<const float4*>(Wo + (size_t)(n0 + arow + 64) * Dd + k0 + acol);
        __syncthreads();
        As[acol + 0][arow] = a0.x; As[acol + 1][arow] = a0.y;
        As[acol + 2][arow] = a0.z; As[acol + 3][arow] = a0.w;
        As[acol + 0][arow + 64] = a1.x; As[acol + 1][arow + 64] = a1.y;
        As[acol + 2][arow + 64] = a1.z; As[acol + 3][arow + 64] = a1.w;
        Bs[acol + 0][arow] = w0.x; Bs[acol + 1][arow] = w0.y;
        Bs[acol + 2][arow] = w0.z; Bs[acol + 3][arow] = w0.w;
        Bs[acol + 0][arow + 64] = w1.x; Bs[acol + 1][arow + 64] = w1.y;
        Bs[acol + 2][arow + 64] = w1.z; Bs[acol + 3][arow + 64] = w1.w;
        __syncthreads();
#pragma unroll
        for (int k = 0; k < 16; k++) {
            float ra[8], rb[8];
#pragma unroll
            for (int i = 0; i < 8; i++) ra[i] = As[k][ty * 8 + i];
#pragma unroll
            for (int j = 0; j < 8; j++) rb[j] = Bs[k][tx * 8 + j];
#pragma unroll
            for (int i = 0; i < 8; i++)
#pragma unroll
                for (int j = 0; j < 8; j++) acc[i][j] += ra[i] * rb[j];
        }
    }

    float4 bb0 = *reinterpret_cast<const float4*>(ob + n0 + tx * 8);
    float4 bb1 = *reinterpret_cast<const float4*>(ob + n0 + tx * 8 + 4);
#pragma unroll
    for (int i = 0; i < 8; i++) {
        const int row = m0 + ty * 8 + i;
        float4 o0 = make_float4(acc[i][0] + bb0.x, acc[i][1] + bb0.y,
                                acc[i][2] + bb0.z, acc[i][3] + bb0.w);
        float4 o1 = make_float4(acc[i][4] + bb1.x, acc[i][5] + bb1.y,
                                acc[i][6] + bb1.z, acc[i][7] + bb1.w);
        *reinterpret_cast<float4*>(out + (size_t)row * Dd + n0 + tx * 8) = o0;
        *reinterpret_cast<float4*>(out + (size_t)row * Dd + n0 + tx * 8 + 4) = o1;
    }
}

// ---------------------------------------------------------------------------
extern "C" void kernel_launch(void* const* d_in, const int* in_sizes, int n_in,
                              void* d_out, int out_size)
{
    const float* query  = (const float*)d_in[0];
    const float* biasTS = (const float*)d_in[1];
    const float* wq = (const float*)d_in[2];
    const float* bq = (const float*)d_in[3];
    const float* wk = (const float*)d_in[4];
    const float* bk = (const float*)d_in[5];
    const float* wv = (const float*)d_in[6];
    const float* bv = (const float*)d_in[7];
    const float* wo = (const float*)d_in[8];
    const float* obias = (const float*)d_in[9];

    float* data_out  = (float*)d_out;                       // [B,T,D] = 8388608
    float* probs_out = data_out + (size_t)Bb * Tt * Dd;     // [B,N,T,S] = 134217728

    dim3 blk(256);
    proj_kernel<<<dim3(Dd / 128, (Bb * Tt) / 128, 3), blk>>>(query, wq, wk, wv, bq, bk, bv);
    logits_stats_kernel<<<dim3(Tt / 128, Bb * Nh), blk>>>(biasTS, probs_out);
    softmax_pv_kernel<<<dim3(Tt / 128, Bb * Nh), blk>>>(probs_out);
    oproj_kernel<<<dim3(Dd / 128, (Bb * Tt) / 128), blk>>>(wo, obias, data_out);
}

// round 2
// speedup vs baseline: 1.1347x; 1.1347x over previous
#include <cuda_runtime.h>

// Problem constants
constexpr int Bb = 2;
constexpr int Tt = 2048;
constexpr int Dd = 2048;
constexpr int Nh = 16;
constexpr int Hd = 128;
constexpr int Ss = Tt;
constexpr float QSCALE = 0.08838834764831845f; // 1/sqrt(128)

// Scratch (device globals — no allocation allowed)
__device__ float g_q[(size_t)Bb * Tt * Dd];
__device__ float g_k[(size_t)Bb * Tt * Dd];
__device__ float g_v[(size_t)Bb * Tt * Dd];
__device__ float g_ctx[(size_t)Bb * Tt * Dd];
__device__ float g_m[(size_t)Bb * Nh * Tt];
__device__ float g_l[(size_t)Bb * Nh * Tt];

// Shared tiles padded to 132 floats/row: 528B row stride keeps float4 alignment
// and makes the transposed STS pattern (bank = arow + acol*4 + c*4) conflict-free.
#define SMEM_LD 132

// Fragment loads: conflict-free LDS.128. Thread (tx,ty) owns rows
// {ty*4..+3, 64+ty*4..+3} x cols {tx*4..+3, 64+tx*4..+3}.
#define LOAD_FRAGS(As, Bs, k)                                              \
    float4 fa0 = *reinterpret_cast<const float4*>(&As[k][ty * 4]);         \
    float4 fa1 = *reinterpret_cast<const float4*>(&As[k][64 + ty * 4]);    \
    float4 fb0 = *reinterpret_cast<const float4*>(&Bs[k][tx * 4]);         \
    float4 fb1 = *reinterpret_cast<const float4*>(&Bs[k][64 + tx * 4]);    \
    float ra[8] = {fa0.x, fa0.y, fa0.z, fa0.w, fa1.x, fa1.y, fa1.z, fa1.w};\
    float rb[8] = {fb0.x, fb0.y, fb0.z, fb0.w, fb1.x, fb1.y, fb1.z, fb1.w};

#define FMA_8x8()                                                          \
    _Pragma("unroll")                                                      \
    for (int i = 0; i < 8; i++)                                            \
        _Pragma("unroll")                                                  \
        for (int j = 0; j < 8; j++) acc[i][j] += ra[i] * rb[j];

// ---------------------------------------------------------------------------
// Kernel 1: fused QKV projection.  C = X @ W (+bias)(*scale)
// ---------------------------------------------------------------------------
__global__ __launch_bounds__(256, 2)
void proj_kernel(const float* __restrict__ X,
                 const float* __restrict__ Wq, const float* __restrict__ Wk,
                 const float* __restrict__ Wv,
                 const float* __restrict__ bq, const float* __restrict__ bk,
                 const float* __restrict__ bv)
{
    const int z = blockIdx.z;
    const float* __restrict__ W    = (z == 0) ? Wq : (z == 1) ? Wk : Wv;
    const float* __restrict__ bias = (z == 0) ? bq : (z == 1) ? bk : bv;
    float* __restrict__ Out        = (z == 0) ? g_q : (z == 1) ? g_k : g_v;
    const float scale = (z == 0) ? QSCALE : 1.0f;

    __shared__ float As[16][SMEM_LD];
    __shared__ float Bs[16][SMEM_LD];

    const int tid = threadIdx.x;
    const int tx = tid & 15;
    const int ty = tid >> 4;
    const int m0 = blockIdx.y * 128;
    const int n0 = blockIdx.x * 128;

    const int arow = tid >> 2;          // 0..63
    const int acol = (tid & 3) << 2;    // 0,4,8,12
    const int brow = tid >> 5;          // 0..7
    const int bcol = (tid & 31) << 2;   // 0..124

    float acc[8][8];
#pragma unroll
    for (int i = 0; i < 8; i++)
#pragma unroll
        for (int j = 0; j < 8; j++) acc[i][j] = 0.f;

    for (int k0 = 0; k0 < Dd; k0 += 16) {
        float4 a0 = *reinterpret_cast<const float4*>(X + (size_t)(m0 + arow) * Dd + k0 + acol);
        float4 a1 = *reinterpret_cast<const float4*>(X + (size_t)(m0 + arow + 64) * Dd + k0 + acol);
        float4 b0 = *reinterpret_cast<const float4*>(W + (size_t)(k0 + brow) * Dd + n0 + bcol);
        float4 b1 = *reinterpret_cast<const float4*>(W + (size_t)(k0 + brow + 8) * Dd + n0 + bcol);
        __syncthreads();
        As[acol + 0][arow] = a0.x; As[acol + 1][arow] = a0.y;
        As[acol + 2][arow] = a0.z; As[acol + 3][arow] = a0.w;
        As[acol + 0][arow + 64] = a1.x; As[acol + 1][arow + 64] = a1.y;
        As[acol + 2][arow + 64] = a1.z; As[acol + 3][arow + 64] = a1.w;
        *reinterpret_cast<float4*>(&Bs[brow][bcol]) = b0;
        *reinterpret_cast<float4*>(&Bs[brow + 8][bcol]) = b1;
        __syncthreads();
#pragma unroll
        for (int k = 0; k < 16; k++) {
            LOAD_FRAGS(As, Bs, k)
            FMA_8x8()
        }
    }

    float4 bb0 = *reinterpret_cast<const float4*>(bias + n0 + tx * 4);
    float4 bb1 = *reinterpret_cast<const float4*>(bias + n0 + 64 + tx * 4);
#pragma unroll
    for (int i = 0; i < 8; i++) {
        const int row = m0 + ((i < 4) ? ty * 4 + i : 64 + ty * 4 + i - 4);
        float4 o0 = make_float4((acc[i][0] + bb0.x) * scale, (acc[i][1] + bb0.y) * scale,
                                (acc[i][2] + bb0.z) * scale, (acc[i][3] + bb0.w) * scale);
        float4 o1 = make_float4((acc[i][4] + bb1.x) * scale, (acc[i][5] + bb1.y) * scale,
                                (acc[i][6] + bb1.z) * scale, (acc[i][7] + bb1.w) * scale);
        *reinterpret_cast<float4*>(Out + (size_t)row * Dd + n0 + tx * 4) = o0;
        *reinterpret_cast<float4*>(Out + (size_t)row * Dd + n0 + 64 + tx * 4) = o1;
    }
}

// ---------------------------------------------------------------------------
// Kernel 2: logits = Q_bn @ K_bn^T + bias (raw -> probs region) + online stats.
// ---------------------------------------------------------------------------
__global__ __launch_bounds__(256, 2)
void logits_stats_kernel(const float* __restrict__ biasTS, float* __restrict__ probs)
{
    const int bn = blockIdx.y;
    const int b = bn >> 4;
    const int n = bn & 15;
    const int t0 = blockIdx.x * 128;

    const float* __restrict__ Qp = g_q + (size_t)b * Tt * Dd + n * Hd;
    const float* __restrict__ Kp = g_k + (size_t)b * Tt * Dd + n * Hd;
    float* __restrict__ Lout = probs + (size_t)bn * Tt * Ss;

    __shared__ float As[16][SMEM_LD];
    __shared__ float Bs[16][SMEM_LD];
    __shared__ float red_m[128][16];
    __shared__ float red_s[128][16];

    const int tid = threadIdx.x;
    const int tx = tid & 15;
    const int ty = tid >> 4;
    const int arow = tid >> 2;
    const int acol = (tid & 3) << 2;

    float m_loc[8], s_loc[8];
#pragma unroll
    for (int i = 0; i < 8; i++) { m_loc[i] = -1e30f; s_loc[i] = 0.f; }

    for (int st = 0; st < 16; st++) {
        const int s0 = st * 128;
        float acc[8][8];
#pragma unroll
        for (int i = 0; i < 8; i++)
#pragma unroll
            for (int j = 0; j < 8; j++) acc[i][j] = 0.f;

        for (int k0 = 0; k0 < Hd; k0 += 16) {
            float4 a0 = *reinterpret_cast<const float4*>(Qp + (size_t)(t0 + arow) * Dd + k0 + acol);
            float4 a1 = *reinterpret_cast<const float4*>(Qp + (size_t)(t0 + arow + 64) * Dd + k0 + acol);
            float4 b0 = *reinterpret_cast<const float4*>(Kp + (size_t)(s0 + arow) * Dd + k0 + acol);
            float4 b1 = *reinterpret_cast<const float4*>(Kp + (size_t)(s0 + arow + 64) * Dd + k0 + acol);
            __syncthreads();
            As[acol + 0][arow] = a0.x; As[acol + 1][arow] = a0.y;
            As[acol + 2][arow] = a0.z; As[acol + 3][arow] = a0.w;
            As[acol + 0][arow + 64] = a1.x; As[acol + 1][arow + 64] = a1.y;
            As[acol + 2][arow + 64] = a1.z; As[acol + 3][arow + 64] = a1.w;
            Bs[acol + 0][arow] = b0.x; Bs[acol + 1][arow] = b0.y;
            Bs[acol + 2][arow] = b0.z; Bs[acol + 3][arow] = b0.w;
            Bs[acol + 0][arow + 64] = b1.x; Bs[acol + 1][arow + 64] = b1.y;
            Bs[acol + 2][arow + 64] = b1.z; Bs[acol + 3][arow + 64] = b1.w;
            __syncthreads();
#pragma unroll
            for (int k = 0; k < 16; k++) {
                LOAD_FRAGS(As, Bs, k)
                FMA_8x8()
            }
        }

        // bias add, online stats, raw-logit store
#pragma unroll
        for (int i = 0; i < 8; i++) {
            const int lr = (i < 4) ? ty * 4 + i : 64 + ty * 4 + i - 4;
            const int row = t0 + lr;
            const float* bp = biasTS + (size_t)row * Ss + s0;
            float4 c0 = *reinterpret_cast<const float4*>(bp + tx * 4);
            float4 c1 = *reinterpret_cast<const float4*>(bp + 64 + tx * 4);
            float l[8];
            l[0] = acc[i][0] + c0.x; l[1] = acc[i][1] + c0.y;
            l[2] = acc[i][2] + c0.z; l[3] = acc[i][3] + c0.w;
            l[4] = acc[i][4] + c1.x; l[5] = acc[i][5] + c1.y;
            l[6] = acc[i][6] + c1.z; l[7] = acc[i][7] + c1.w;
            float tm = l[0];
#pragma unroll
            for (int j = 1; j < 8; j++) tm = fmaxf(tm, l[j]);
            float m_new = fmaxf(m_loc[i], tm);
            float corr = __expf(m_loc[i] - m_new);
            float add = 0.f;
#pragma unroll
            for (int j = 0; j < 8; j++) add += __expf(l[j] - m_new);
            s_loc[i] = s_loc[i] * corr + add;
            m_loc[i] = m_new;
            *reinterpret_cast<float4*>(Lout + (size_t)row * Ss + s0 + tx * 4) =
                make_float4(l[0], l[1], l[2], l[3]);
            *reinterpret_cast<float4*>(Lout + (size_t)row * Ss + s0 + 64 + tx * 4) =
                make_float4(l[4], l[5], l[6], l[7]);
        }
    }

    // cross-thread (tx) merge of per-row stats
#pragma unroll
    for (int i = 0; i < 8; i++) {
        const int lr = (i < 4) ? ty * 4 + i : 64 + ty * 4 + i - 4;
        red_m[lr][tx] = m_loc[i];
        red_s[lr][tx] = s_loc[i];
    }
    __syncthreads();
    if (tid < 128) {
        float m = -1e30f;
#pragma unroll
        for (int x = 0; x < 16; x++) m = fmaxf(m, red_m[tid][x]);
        float s = 0.f;
#pragma unroll
        for (int x = 0; x < 16; x++) s += red_s[tid][x] * __expf(red_m[tid][x] - m);
        g_m[(size_t)bn * Tt + t0 + tid] = m;
        g_l[(size_t)bn * Tt + t0 + tid] = s;
    }
}

// ---------------------------------------------------------------------------
// Kernel 3: in-place softmax on probs + fused PV -> g_ctx (btnh layout).
// ---------------------------------------------------------------------------
__global__ __launch_bounds__(256, 2)
void softmax_pv_kernel(float* __restrict__ probs)
{
    const int bn = blockIdx.y;
    const int b = bn >> 4;
    const int n = bn & 15;
    const int t0 = blockIdx.x * 128;

    const float* __restrict__ Vp = g_v + (size_t)b * Tt * Dd + n * Hd;
    float* __restrict__ Lp = probs + (size_t)bn * Tt * Ss;

    __shared__ float As[16][SMEM_LD];
    __shared__ float Bs[16][SMEM_LD];
    __shared__ float sm_m[128];
    __shared__ float sm_inv[128];

    const int tid = threadIdx.x;
    const int tx = tid & 15;
    const int ty = tid >> 4;
    const int arow = tid >> 2;          // 0..63 (t rows)
    const int acol = (tid & 3) << 2;    // s offset in chunk
    const int vrow = tid >> 5;          // 0..7 (s rows)
    const int vcol = (tid & 31) << 2;   // h

    if (tid < 128) {
        sm_m[tid] = g_m[(size_t)bn * Tt + t0 + tid];
        sm_inv[tid] = 1.0f / g_l[(size_t)bn * Tt + t0 + tid];
    }
    __syncthreads();

    float acc[8][8];
#pragma unroll
    for (int i = 0; i < 8; i++)
#pragma unroll
        for (int j = 0; j < 8; j++) acc[i][j] = 0.f;

    for (int s0 = 0; s0 < Ss; s0 += 16) {
        float4 a0 = *reinterpret_cast<const float4*>(Lp + (size_t)(t0 + arow) * Ss + s0 + acol);
        float4 a1 = *reinterpret_cast<const float4*>(Lp + (size_t)(t0 + arow + 64) * Ss + s0 + acol);
        const float m0v = sm_m[arow],      i0v = sm_inv[arow];
        const float m1v = sm_m[arow + 64], i1v = sm_inv[arow + 64];
        a0.x = __expf(a0.x - m0v) * i0v; a0.y = __expf(a0.y - m0v) * i0v;
        a0.z = __expf(a0.z - m0v) * i0v; a0.w = __expf(a0.w - m0v) * i0v;
        a1.x = __expf(a1.x - m1v) * i1v; a1.y = __expf(a1.y - m1v) * i1v;
        a1.z = __expf(a1.z - m1v) * i1v; a1.w = __expf(a1.w - m1v) * i1v;
        *reinterpret_cast<float4*>(Lp + (size_t)(t0 + arow) * Ss + s0 + acol) = a0;
        *reinterpret_cast<float4*>(Lp + (size_t)(t0 + arow + 64) * Ss + s0 + acol) = a1;

        float4 v0 = *reinterpret_cast<const float4*>(Vp + (size_t)(s0 + vrow) * Dd + vcol);
        float4 v1 = *reinterpret_cast<const float4*>(Vp + (size_t)(s0 + vrow + 8) * Dd + vcol);
        __syncthreads();
        As[acol + 0][arow] = a0.x; As[acol + 1][arow] = a0.y;
        As[acol + 2][arow] = a0.z; As[acol + 3][arow] = a0.w;
        As[acol + 0][arow + 64] = a1.x; As[acol + 1][arow + 64] = a1.y;
        As[acol + 2][arow + 64] = a1.z; As[acol + 3][arow + 64] = a1.w;
        *reinterpret_cast<float4*>(&Bs[vrow][vcol]) = v0;
        *reinterpret_cast<float4*>(&Bs[vrow + 8][vcol]) = v1;
        __syncthreads();
#pragma unroll
        for (int k = 0; k < 16; k++) {
            LOAD_FRAGS(As, Bs, k)
            FMA_8x8()
        }
    }

#pragma unroll
    for (int i = 0; i < 8; i++) {
        const int row = t0 + ((i < 4) ? ty * 4 + i : 64 + ty * 4 + i - 4);
        float* cp = g_ctx + (size_t)(b * Tt + row) * Dd + n * Hd;
        *reinterpret_cast<float4*>(cp + tx * 4) =
            make_float4(acc[i][0], acc[i][1], acc[i][2], acc[i][3]);
        *reinterpret_cast<float4*>(cp + 64 + tx * 4) =
            make_float4(acc[i][4], acc[i][5], acc[i][6], acc[i][7]);
    }
}

// ---------------------------------------------------------------------------
// Kernel 4: output projection (NT GEMM): data = ctx @ Wo^T + ob
// ---------------------------------------------------------------------------
__global__ __launch_bounds__(256, 2)
void oproj_kernel(const float* __restrict__ Wo, const float* __restrict__ ob,
                  float* __restrict__ out)
{
    __shared__ float As[16][SMEM_LD];
    __shared__ float Bs[16][SMEM_LD];

    const int tid = threadIdx.x;
    const int tx = tid & 15;
    const int ty = tid >> 4;
    const int m0 = blockIdx.y * 128;
    const int n0 = blockIdx.x * 128;

    const int arow = tid >> 2;
    const int acol = (tid & 3) << 2;

    float acc[8][8];
#pragma unroll
    for (int i = 0; i < 8; i++)
#pragma unroll
        for (int j = 0; j < 8; j++) acc[i][j] = 0.f;

    for (int k0 = 0; k0 < Dd; k0 += 16) {
        float4 a0 = *reinterpret_cast<const float4*>(g_ctx + (size_t)(m0 + arow) * Dd + k0 + acol);
        float4 a1 = *reinterpret_cast<const float4*>(g_ctx + (size_t)(m0 + arow + 64) * Dd + k0 + acol);
        float4 w0 = *reinterpret_cast<const float4*>(Wo + (size_t)(n0 + arow) * Dd + k0 + acol);
        float4 w1 = *reinterpret_cast<const float4*>(Wo + (size_t)(n0 + arow + 64) * Dd + k0 + acol);
        __syncthreads();
        As[acol + 0][arow] = a0.x; As[acol + 1][arow] = a0.y;
        As[acol + 2][arow] = a0.z; As[acol + 3][arow] = a0.w;
        As[acol + 0][arow + 64] = a1.x; As[acol + 1][arow + 64] = a1.y;
        As[acol + 2][arow + 64] = a1.z; As[acol + 3][arow + 64] = a1.w;
        Bs[acol + 0][arow] = w0.x; Bs[acol + 1][arow] = w0.y;
        Bs[acol + 2][arow] = w0.z; Bs[acol + 3][arow] = w0.w;
        Bs[acol + 0][arow + 64] = w1.x; Bs[acol + 1][arow + 64] = w1.y;
        Bs[acol + 2][arow + 64] = w1.z; Bs[acol + 3][arow + 64] = w1.w;
        __syncthreads();
#pragma unroll
        for (int k = 0; k < 16; k++) {
            LOAD_FRAGS(As, Bs, k)
            FMA_8x8()
        }
    }

    float4 bb0 = *reinterpret_cast<const float4*>(ob + n0 + tx * 4);
    float4 bb1 = *reinterpret_cast<const float4*>(ob + n0 + 64 + tx * 4);
#pragma unroll
    for (int i = 0; i < 8; i++) {
        const int row = m0 + ((i < 4) ? ty * 4 + i : 64 + ty * 4 + i - 4);
        float4 o0 = make_float4(acc[i][0] + bb0.x, acc[i][1] + bb0.y,
                                acc[i][2] + bb0.z, acc[i][3] + bb0.w);
        float4 o1 = make_float4(acc[i][4] + bb1.x, acc[i][5] + bb1.y,
                                acc[i][6] + bb1.z, acc[i][7] + bb1.w);
        *reinterpret_cast<float4*>(out + (size_t)row * Dd + n0 + tx * 4) = o0;
        *reinterpret_cast<float4*>(out + (size_t)row * Dd + n0 + 64 + tx * 4) = o1;
    }
}

// ---------------------------------------------------------------------------
extern "C" void kernel_launch(void* const* d_in, const int* in_sizes, int n_in,
                              void* d_out, int out_size)
{
    const float* query  = (const float*)d_in[0];
    const float* biasTS = (const float*)d_in[1];
    const float* wq = (const float*)d_in[2];
    const float* bq = (const float*)d_in[3];
    const float* wk = (const float*)d_in[4];
    const float* bk = (const float*)d_in[5];
    const float* wv = (const float*)d_in[6];
    const float* bv = (const float*)d_in[7];
    const float* wo = (const float*)d_in[8];
    const float* obias = (const float*)d_in[9];

    float* data_out  = (float*)d_out;                       // [B,T,D] = 8388608
    float* probs_out = data_out + (size_t)Bb * Tt * Dd;     // [B,N,T,S] = 134217728

    dim3 blk(256);
    proj_kernel<<<dim3(Dd / 128, (Bb * Tt) / 128, 3), blk>>>(query, wq, wk, wv, bq, bk, bv);
    logits_stats_kernel<<<dim3(Tt / 128, Bb * Nh), blk>>>(biasTS, probs_out);
    softmax_pv_kernel<<<dim3(Tt / 128, Bb * Nh), blk>>>(probs_out);
    oproj_kernel<<<dim3(Dd / 128, (Bb * Tt) / 128), blk>>>(wo, obias, data_out);
}

// round 4
// speedup vs baseline: 1.7930x; 1.5802x over previous
#include <cuda_runtime.h>
#include <cuda_bf16.h>
#include <cstdint>

// Problem constants
constexpr int Bb = 2;
constexpr int Tt = 2048;
constexpr int Dd = 2048;
constexpr int Nh = 16;
constexpr int Hd = 128;
constexpr int Ss = 2048;
constexpr float QSCALE = 0.08838834764831845f; // 1/sqrt(128)

// Scratch (device globals — no allocation allowed)
__device__ float g_q[(size_t)Bb * Tt * Dd];
__device__ float g_k[(size_t)Bb * Tt * Dd];
__device__ float g_v[(size_t)Bb * Tt * Dd];
__device__ float g_ctx[(size_t)Bb * Tt * Dd];
__device__ float g_m[(size_t)Bb * Nh * Tt];
__device__ float g_l[(size_t)Bb * Nh * Tt];
__device__ float g_wt[(size_t)3 * Dd * Dd];   // transposed W_{q,k,v}: [n][k]

// ===========================================================================
// Helpers
// ===========================================================================
__device__ __forceinline__ uint32_t smem_u32(const void* p) {
    return (uint32_t)__cvta_generic_to_shared(p);
}
__device__ __forceinline__ void ldsm4(uint32_t* r, uint32_t addr) {
    asm volatile("ldmatrix.sync.aligned.m8n8.x4.shared.b16 {%0,%1,%2,%3}, [%4];"
                 : "=r"(r[0]), "=r"(r[1]), "=r"(r[2]), "=r"(r[3]) : "r"(addr));
}
__device__ __forceinline__ void mma_bf16(float* c, const uint32_t* a, const uint32_t* b) {
    asm volatile(
        "mma.sync.aligned.m16n8k16.row.col.f32.bf16.bf16.f32 "
        "{%0,%1,%2,%3}, {%4,%5,%6,%7}, {%8,%9}, {%0,%1,%2,%3};"
        : "+f"(c[0]), "+f"(c[1]), "+f"(c[2]), "+f"(c[3])
        : "r"(a[0]), "r"(a[1]), "r"(a[2]), "r"(a[3]), "r"(b[0]), "r"(b[1]));
}
// Markidis bf16 split of a float pair -> packed hi (bf16x2) and lo (bf16x2)
__device__ __forceinline__ void split2(float x0, float x1, uint32_t& hi, uint32_t& lo) {
    __nv_bfloat162 h2 = __floats2bfloat162_rn(x0, x1);   // .x=x0(lo half), .y=x1
    float r0 = x0 - __bfloat162float(h2.x);
    float r1 = x1 - __bfloat162float(h2.y);
    __nv_bfloat162 l2 = __floats2bfloat162_rn(r0, r1);
    hi = *reinterpret_cast<uint32_t*>(&h2);
    lo = *reinterpret_cast<uint32_t*>(&l2);
}

// smem tile geometry: 128 rows x 32 bf16 (k), row stride 40 bf16 (80B) = 20 u32.
// Stride 80B = 20 banks -> ldmatrix 8-row phases hit all 32 banks exactly once.
constexpr int STR_U32 = 20;
constexpr int STR_B   = 80;

// ===========================================================================
// bf16-split-3 mma.sync GEMM: Out[m0..+128][n0..+128] =
//   A[m][k] (k-major) x Bt[n][k] (k-major), K=2048, (+bias)*scale.
// 256 threads = 8 warps; warp grid 2(m) x 4(n); warp tile 64x32.
// ===========================================================================
__device__ __forceinline__ void mma_gemm(const float* __restrict__ A,
                                         const float* __restrict__ Bt,
                                         const float* __restrict__ bias,
                                         float* __restrict__ Out,
                                         float scale, int m0, int n0)
{
    __shared__ __align__(16) uint32_t sAh[128 * STR_U32];
    __shared__ __align__(16) uint32_t sAl[128 * STR_U32];
    __shared__ __align__(16) uint32_t sBh[128 * STR_U32];
    __shared__ __align__(16) uint32_t sBl[128 * STR_U32];

    const int tid = threadIdx.x;
    const int wid = tid >> 5;
    const int l = tid & 31;
    const int m_off = (wid & 1) * 64;
    const int n_off = (wid >> 1) * 32;

    // Global load mapping: per j (0..3), row = lrow + 32j, cols kq..kq+3 of chunk.
    const int lrow = tid >> 3;            // 0..31
    const int kq = (tid & 7) * 4;         // 0,4,...,28
    const float* pA = A + (size_t)(m0 + lrow) * Dd + kq;
    const float* pB = Bt + (size_t)(n0 + lrow) * Dd + kq;

    // ldmatrix lane address components
    const uint32_t SAh = smem_u32(sAh), SAl = smem_u32(sAl);
    const uint32_t SBh = smem_u32(sBh), SBl = smem_u32(sBl);
    const uint32_t aoff = (uint32_t)((m_off + (l & 15)) * STR_B + ((l >> 4) << 3) * 2);
    const uint32_t boff = (uint32_t)((n_off + (l & 7) + ((l >> 4) << 3)) * STR_B +
                                     (((l >> 3) & 1) * 8) * 2);

    float acc[4][4][4];
#pragma unroll
    for (int mt = 0; mt < 4; mt++)
#pragma unroll
        for (int nt = 0; nt < 4; nt++)
#pragma unroll
            for (int q = 0; q < 4; q++) acc[mt][nt][q] = 0.f;

#pragma unroll 1
    for (int c = 0; c < 64; c++) {
        float4 va[4], vb[4];
#pragma unroll
        for (int j = 0; j < 4; j++) {
            va[j] = *reinterpret_cast<const float4*>(pA + (size_t)j * 32 * Dd + c * 32);
            vb[j] = *reinterpret_cast<const float4*>(pB + (size_t)j * 32 * Dd + c * 32);
        }
        __syncthreads();
#pragma unroll
        for (int j = 0; j < 4; j++) {
            const int sidx = (lrow + j * 32) * STR_U32 + (kq >> 1);
            uint32_t h0, h1, l0, l1;
            split2(va[j].x, va[j].y, h0, l0);
            split2(va[j].z, va[j].w, h1, l1);
            *reinterpret_cast<uint2*>(&sAh[sidx]) = make_uint2(h0, h1);
            *reinterpret_cast<uint2*>(&sAl[sidx]) = make_uint2(l0, l1);
            split2(vb[j].x, vb[j].y, h0, l0);
            split2(vb[j].z, vb[j].w, h1, l1);
            *reinterpret_cast<uint2*>(&sBh[sidx]) = make_uint2(h0, h1);
            *reinterpret_cast<uint2*>(&sBl[sidx]) = make_uint2(l0, l1);
        }
        __syncthreads();

#pragma unroll
        for (int ks = 0; ks < 2; ks++) {
            uint32_t Ah[4][4], Al[4][4], Bh[2][4], Bl[2][4];
#pragma unroll
            for (int mt = 0; mt < 4; mt++) {
                ldsm4(Ah[mt], SAh + aoff + mt * 16 * STR_B + ks * 32);
                ldsm4(Al[mt], SAl + aoff + mt * 16 * STR_B + ks * 32);
            }
#pragma unroll
            for (int np = 0; np < 2; np++) {
                ldsm4(Bh[np], SBh + boff + np * 16 * STR_B + ks * 32);
                ldsm4(Bl[np], SBl + boff + np * 16 * STR_B + ks * 32);
            }
#pragma unroll
            for (int mt = 0; mt < 4; mt++)
#pragma unroll
                for (int nt = 0; nt < 4; nt++) {
                    const uint32_t* bh = &Bh[nt >> 1][(nt & 1) * 2];
                    const uint32_t* bl = &Bl[nt >> 1][(nt & 1) * 2];
                    mma_bf16(acc[mt][nt], Ah[mt], bh);   // hi*hi
                    mma_bf16(acc[mt][nt], Ah[mt], bl);   // hi*lo
                    mma_bf16(acc[mt][nt], Al[mt], bh);   // lo*hi
                }
        }
    }

    // Epilogue: c0,c1 = (row g, cols 2tg..+1); c2,c3 = (row g+8)
    const int g = l >> 2, tg = l & 3;
#pragma unroll
    for (int mt = 0; mt < 4; mt++) {
        const int r0 = m0 + m_off + mt * 16 + g;
#pragma unroll
        for (int nt = 0; nt < 4; nt++) {
            const int col = n0 + n_off + nt * 8 + tg * 2;
            const float b0v = bias[col], b1v = bias[col + 1];
            *reinterpret_cast<float2*>(Out + (size_t)r0 * Dd + col) =
                make_float2((acc[mt][nt][0] + b0v) * scale, (acc[mt][nt][1] + b1v) * scale);
            *reinterpret_cast<float2*>(Out + (size_t)(r0 + 8) * Dd + col) =
                make_float2((acc[mt][nt][2] + b0v) * scale, (acc[mt][nt][3] + b1v) * scale);
        }
    }
}

__global__ __launch_bounds__(256)
void mma_proj_kernel(const float* __restrict__ X, const float* __restrict__ bq,
                     const float* __restrict__ bk, const float* __restrict__ bv)
{
    const int z = blockIdx.z;
    const float* Bt = g_wt + (size_t)z * Dd * Dd;
    const float* bias = (z == 0) ? bq : (z == 1) ? bk : bv;
    float* Out = (z == 0) ? g_q : (z == 1) ? g_k : g_v;
    const float scale = (z == 0) ? QSCALE : 1.0f;
    mma_gemm(X, Bt, bias, Out, scale, blockIdx.y * 128, blockIdx.x * 128);
}

__global__ __launch_bounds__(256)
void mma_oproj_kernel(const float* __restrict__ Wo, const float* __restrict__ ob,
                      float* __restrict__ out)
{
    mma_gemm(g_ctx, Wo, ob, out, 1.0f, blockIdx.y * 128, blockIdx.x * 128);
}

// ===========================================================================
// One-time W transpose: g_wt[z][n][k] = W_z[k][n]
// ===========================================================================
__global__ void transpose_w_kernel(const float* __restrict__ Wq,
                                   const float* __restrict__ Wk,
                                   const float* __restrict__ Wv)
{
    __shared__ float ts[32][33];
    const int z = blockIdx.z;
    const float* W = (z == 0) ? Wq : (z == 1) ? Wk : Wv;
    float* Wt = g_wt + (size_t)z * Dd * Dd;
    const int bx = blockIdx.x * 32, by = blockIdx.y * 32;
    const int tx = threadIdx.x, ty = threadIdx.y;
#pragma unroll
    for (int r = 0; r < 32; r += 8)
        ts[ty + r][tx] = W[(size_t)(by + ty + r) * Dd + bx + tx];
    __syncthreads();
#pragma unroll
    for (int r = 0; r < 32; r += 8)
        Wt[(size_t)(bx + ty + r) * Dd + by + tx] = ts[tx][ty + r];
}

// ===========================================================================
// SIMT attention kernels (unchanged from R2)
// ===========================================================================
#define SMEM_LD 132

#define LOAD_FRAGS(As, Bs, k)                                              \
    float4 fa0 = *reinterpret_cast<const float4*>(&As[k][ty * 4]);         \
    float4 fa1 = *reinterpret_cast<const float4*>(&As[k][64 + ty * 4]);    \
    float4 fb0 = *reinterpret_cast<const float4*>(&Bs[k][tx * 4]);         \
    float4 fb1 = *reinterpret_cast<const float4*>(&Bs[k][64 + tx * 4]);    \
    float ra[8] = {fa0.x, fa0.y, fa0.z, fa0.w, fa1.x, fa1.y, fa1.z, fa1.w};\
    float rb[8] = {fb0.x, fb0.y, fb0.z, fb0.w, fb1.x, fb1.y, fb1.z, fb1.w};

#define FMA_8x8()                                                          \
    _Pragma("unroll")                                                      \
    for (int i = 0; i < 8; i++)                                            \
        _Pragma("unroll")                                                  \
        for (int j = 0; j < 8; j++) acc[i][j] += ra[i] * rb[j];

__global__ __launch_bounds__(256, 2)
void logits_stats_kernel(const float* __restrict__ biasTS, float* __restrict__ probs)
{
    const int bn = blockIdx.y;
    const int b = bn >> 4;
    const int n = bn & 15;
    const int t0 = blockIdx.x * 128;

    const float* __restrict__ Qp = g_q + (size_t)b * Tt * Dd + n * Hd;
    const float* __restrict__ Kp = g_k + (size_t)b * Tt * Dd + n * Hd;
    float* __restrict__ Lout = probs + (size_t)bn * Tt * Ss;

    __shared__ float As[16][SMEM_LD];
    __shared__ float Bs[16][SMEM_LD];
    __shared__ float red_m[128][16];
    __shared__ float red_s[128][16];

    const int tid = threadIdx.x;
    const int tx = tid & 15;
    const int ty = tid >> 4;
    const int arow = tid >> 2;
    const int acol = (tid & 3) << 2;

    float m_loc[8], s_loc[8];
#pragma unroll
    for (int i = 0; i < 8; i++) { m_loc[i] = -1e30f; s_loc[i] = 0.f; }

    for (int st = 0; st < 16; st++) {
        const int s0 = st * 128;
        float acc[8][8];
#pragma unroll
        for (int i = 0; i < 8; i++)
#pragma unroll
            for (int j = 0; j < 8; j++) acc[i][j] = 0.f;

        for (int k0 = 0; k0 < Hd; k0 += 16) {
            float4 a0 = *reinterpret_cast<const float4*>(Qp + (size_t)(t0 + arow) * Dd + k0 + acol);
            float4 a1 = *reinterpret_cast<const float4*>(Qp + (size_t)(t0 + arow + 64) * Dd + k0 + acol);
            float4 b0 = *reinterpret_cast<const float4*>(Kp + (size_t)(s0 + arow) * Dd + k0 + acol);
            float4 b1 = *reinterpret_cast<const float4*>(Kp + (size_t)(s0 + arow + 64) * Dd + k0 + acol);
            __syncthreads();
            As[acol + 0][arow] = a0.x; As[acol + 1][arow] = a0.y;
            As[acol + 2][arow] = a0.z; As[acol + 3][arow] = a0.w;
            As[acol + 0][arow + 64] = a1.x; As[acol + 1][arow + 64] = a1.y;
            As[acol + 2][arow + 64] = a1.z; As[acol + 3][arow + 64] = a1.w;
            Bs[acol + 0][arow] = b0.x; Bs[acol + 1][arow] = b0.y;
            Bs[acol + 2][arow] = b0.z; Bs[acol + 3][arow] = b0.w;
            Bs[acol + 0][arow + 64] = b1.x; Bs[acol + 1][arow + 64] = b1.y;
            Bs[acol + 2][arow + 64] = b1.z; Bs[acol + 3][arow + 64] = b1.w;
            __syncthreads();
#pragma unroll
            for (int k = 0; k < 16; k++) {
                LOAD_FRAGS(As, Bs, k)
                FMA_8x8()
            }
        }

#pragma unroll
        for (int i = 0; i < 8; i++) {
            const int lr = (i < 4) ? ty * 4 + i : 64 + ty * 4 + i - 4;
            const int row = t0 + lr;
            const float* bp = biasTS + (size_t)row * Ss + s0;
            float4 c0 = *reinterpret_cast<const float4*>(bp + tx * 4);
            float4 c1 = *reinterpret_cast<const float4*>(bp + 64 + tx * 4);
            float l[8];
            l[0] = acc[i][0] + c0.x; l[1] = acc[i][1] + c0.y;
            l[2] = acc[i][2] + c0.z; l[3] = acc[i][3] + c0.w;
            l[4] = acc[i][4] + c1.x; l[5] = acc[i][5] + c1.y;
            l[6] = acc[i][6] + c1.z; l[7] = acc[i][7] + c1.w;
            float tm = l[0];
#pragma unroll
            for (int j = 1; j < 8; j++) tm = fmaxf(tm, l[j]);
            float m_new = fmaxf(m_loc[i], tm);
            float corr = __expf(m_loc[i] - m_new);
            float add = 0.f;
#pragma unroll
            for (int j = 0; j < 8; j++) add += __expf(l[j] - m_new);
            s_loc[i] = s_loc[i] * corr + add;
            m_loc[i] = m_new;
            *reinterpret_cast<float4*>(Lout + (size_t)row * Ss + s0 + tx * 4) =
                make_float4(l[0], l[1], l[2], l[3]);
            *reinterpret_cast<float4*>(Lout + (size_t)row * Ss + s0 + 64 + tx * 4) =
                make_float4(l[4], l[5], l[6], l[7]);
        }
    }

#pragma unroll
    for (int i = 0; i < 8; i++) {
        const int lr = (i < 4) ? ty * 4 + i : 64 + ty * 4 + i - 4;
        red_m[lr][tx] = m_loc[i];
        red_s[lr][tx] = s_loc[i];
    }
    __syncthreads();
    if (tid < 128) {
        float m = -1e30f;
#pragma unroll
        for (int x = 0; x < 16; x++) m = fmaxf(m, red_m[tid][x]);
        float s = 0.f;
#pragma unroll
        for (int x = 0; x < 16; x++) s += red_s[tid][x] * __expf(red_m[tid][x] - m);
        g_m[(size_t)bn * Tt + t0 + tid] = m;
        g_l[(size_t)bn * Tt + t0 + tid] = s;
    }
}

__global__ __launch_bounds__(256, 2)
void softmax_pv_kernel(float* __restrict__ probs)
{
    const int bn = blockIdx.y;
    const int b = bn >> 4;
    const int n = bn & 15;
    const int t0 = blockIdx.x * 128;

    const float* __restrict__ Vp = g_v + (size_t)b * Tt * Dd + n * Hd;
    float* __restrict__ Lp = probs + (size_t)bn * Tt * Ss;

    __shared__ float As[16][SMEM_LD];
    __shared__ float Bs[16][SMEM_LD];
    __shared__ float sm_m[128];
    __shared__ float sm_inv[128];

    const int tid = threadIdx.x;
    const int tx = tid & 15;
    const int ty = tid >> 4;
    const int arow = tid >> 2;
    const int acol = (tid & 3) << 2;
    const int vrow = tid >> 5;
    const int vcol = (tid & 31) << 2;

    if (tid < 128) {
        sm_m[tid] = g_m[(size_t)bn * Tt + t0 + tid];
        sm_inv[tid] = 1.0f / g_l[(size_t)bn * Tt + t0 + tid];
    }
    __syncthreads();

    float acc[8][8];
#pragma unroll
    for (int i = 0; i < 8; i++)
#pragma unroll
        for (int j = 0; j < 8; j++) acc[i][j] = 0.f;

    for (int s0 = 0; s0 < Ss; s0 += 16) {
        float4 a0 = *reinterpret_cast<const float4*>(Lp + (size_t)(t0 + arow) * Ss + s0 + acol);
        float4 a1 = *reinterpret_cast<const float4*>(Lp + (size_t)(t0 + arow + 64) * Ss + s0 + acol);
        const float m0v = sm_m[arow],      i0v = sm_inv[arow];
        const float m1v = sm_m[arow + 64], i1v = sm_inv[arow + 64];
        a0.x = __expf(a0.x - m0v) * i0v; a0.y = __expf(a0.y - m0v) * i0v;
        a0.z = __expf(a0.z - m0v) * i0v; a0.w = __expf(a0.w - m0v) * i0v;
        a1.x = __expf(a1.x - m1v) * i1v; a1.y = __expf(a1.y - m1v) * i1v;
        a1.z = __expf(a1.z - m1v) * i1v; a1.w = __expf(a1.w - m1v) * i1v;
        *reinterpret_cast<float4*>(Lp + (size_t)(t0 + arow) * Ss + s0 + acol) = a0;
        *reinterpret_cast<float4*>(Lp + (size_t)(t0 + arow + 64) * Ss + s0 + acol) = a1;

        float4 v0 = *reinterpret_cast<const float4*>(Vp + (size_t)(s0 + vrow) * Dd + vcol);
        float4 v1 = *reinterpret_cast<const float4*>(Vp + (size_t)(s0 + vrow + 8) * Dd + vcol);
        __syncthreads();
        As[acol + 0][arow] = a0.x; As[acol + 1][arow] = a0.y;
        As[acol + 2][arow] = a0.z; As[acol + 3][arow] = a0.w;
        As[acol + 0][arow + 64] = a1.x; As[acol + 1][arow + 64] = a1.y;
        As[acol + 2][arow + 64] = a1.z; As[acol + 3][arow + 64] = a1.w;
        *reinterpret_cast<float4*>(&Bs[vrow][vcol]) = v0;
        *reinterpret_cast<float4*>(&Bs[vrow + 8][vcol]) = v1;
        __syncthreads();
#pragma unroll
        for (int k = 0; k < 16; k++) {
            LOAD_FRAGS(As, Bs, k)
            FMA_8x8()
        }
    }

#pragma unroll
    for (int i = 0; i < 8; i++) {
        const int row = t0 + ((i < 4) ? ty * 4 + i : 64 + ty * 4 + i - 4);
        float* cp = g_ctx + (size_t)(b * Tt + row) * Dd + n * Hd;
        *reinterpret_cast<float4*>(cp + tx * 4) =
            make_float4(acc[i][0], acc[i][1], acc[i][2], acc[i][3]);
        *reinterpret_cast<float4*>(cp + 64 + tx * 4) =
            make_float4(acc[i][4], acc[i][5], acc[i][6], acc[i][7]);
    }
}

// ===========================================================================
extern "C" void kernel_launch(void* const* d_in, const int* in_sizes, int n_in,
                              void* d_out, int out_size)
{
    const float* query  = (const float*)d_in[0];
    const float* biasTS = (const float*)d_in[1];
    const float* wq = (const float*)d_in[2];
    const float* bq = (const float*)d_in[3];
    const float* wk = (const float*)d_in[4];
    const float* bk = (const float*)d_in[5];
    const float* wv = (const float*)d_in[6];
    const float* bv = (const float*)d_in[7];
    const float* wo = (const float*)d_in[8];
    const float* obias = (const float*)d_in[9];

    float* data_out  = (float*)d_out;
    float* probs_out = data_out + (size_t)Bb * Tt * Dd;

    transpose_w_kernel<<<dim3(Dd / 32, Dd / 32, 3), dim3(32, 8)>>>(wq, wk, wv);
    mma_proj_kernel<<<dim3(Dd / 128, (Bb * Tt) / 128, 3), 256>>>(query, bq, bk, bv);
    logits_stats_kernel<<<dim3(Tt / 128, Bb * Nh), 256>>>(biasTS, probs_out);
    softmax_pv_kernel<<<dim3(Tt / 128, Bb * Nh), 256>>>(probs_out);
    mma_oproj_kernel<<<dim3(Dd / 128, (Bb * Tt) / 128), 256>>>(wo, obias, data_out);
}

// round 5
// speedup vs baseline: 2.3269x; 1.2977x over previous
#include <cuda_runtime.h>
#include <cuda_bf16.h>
#include <cstdint>

// Problem constants
constexpr int Bb = 2;
constexpr int Tt = 2048;
constexpr int Dd = 2048;
constexpr int Nh = 16;
constexpr int Hd = 128;
constexpr int Ss = 2048;
constexpr float QSCALE = 0.08838834764831845f; // 1/sqrt(128)

// Scratch (device globals — no allocation allowed)
__device__ float g_q[(size_t)Bb * Tt * Dd];
__device__ float g_k[(size_t)Bb * Tt * Dd];
__device__ float g_v[(size_t)Bb * Tt * Dd];
__device__ float g_vt[(size_t)Bb * Tt * Dd];  // V transposed per head: [bn][h][s]
__device__ float g_ctx[(size_t)Bb * Tt * Dd];
__device__ float g_m[(size_t)Bb * Nh * Tt];
__device__ float g_l[(size_t)Bb * Nh * Tt];
__device__ float g_wt[(size_t)3 * Dd * Dd];   // transposed W_{q,k,v}: [n][k]

// ===========================================================================
// Helpers
// ===========================================================================
__device__ __forceinline__ uint32_t smem_u32(const void* p) {
    return (uint32_t)__cvta_generic_to_shared(p);
}
__device__ __forceinline__ void ldsm4(uint32_t* r, uint32_t addr) {
    asm volatile("ldmatrix.sync.aligned.m8n8.x4.shared.b16 {%0,%1,%2,%3}, [%4];"
                 : "=r"(r[0]), "=r"(r[1]), "=r"(r[2]), "=r"(r[3]) : "r"(addr));
}
__device__ __forceinline__ void mma_bf16(float* c, const uint32_t* a, const uint32_t* b) {
    asm volatile(
        "mma.sync.aligned.m16n8k16.row.col.f32.bf16.bf16.f32 "
        "{%0,%1,%2,%3}, {%4,%5,%6,%7}, {%8,%9}, {%0,%1,%2,%3};"
        : "+f"(c[0]), "+f"(c[1]), "+f"(c[2]), "+f"(c[3])
        : "r"(a[0]), "r"(a[1]), "r"(a[2]), "r"(a[3]), "r"(b[0]), "r"(b[1]));
}
// Markidis bf16 split of a float pair -> packed hi (bf16x2) and lo (bf16x2)
__device__ __forceinline__ void split2(float x0, float x1, uint32_t& hi, uint32_t& lo) {
    __nv_bfloat162 h2 = __floats2bfloat162_rn(x0, x1);
    float r0 = x0 - __bfloat162float(h2.x);
    float r1 = x1 - __bfloat162float(h2.y);
    __nv_bfloat162 l2 = __floats2bfloat162_rn(r0, r1);
    hi = *reinterpret_cast<uint32_t*>(&h2);
    lo = *reinterpret_cast<uint32_t*>(&l2);
}

// smem tile geometry: 128 rows x 32 bf16 (k), row stride 40 bf16 (80B).
constexpr int STR_U32 = 20;
constexpr int STR_B   = 80;

// Common per-thread index bundle for the mma skeleton
#define MMA_IDX                                                             \
    const int tid = threadIdx.x;                                            \
    const int wid = tid >> 5;                                               \
    const int l = tid & 31;                                                 \
    const int m_off = (wid & 1) * 64;                                       \
    const int n_off = (wid >> 1) * 32;                                      \
    const int lrow = tid >> 3;                                              \
    const int kq = (tid & 7) * 4;                                           \
    const uint32_t aoff = (uint32_t)((m_off + (l & 15)) * STR_B +           \
                                     ((l >> 4) << 3) * 2);                  \
    const uint32_t boff = (uint32_t)((n_off + (l & 7) + ((l >> 4) << 3)) *  \
                                     STR_B + (((l >> 3) & 1) * 8) * 2);

#define SPLIT_STORE_A(v, j)                                                 \
    {                                                                       \
        const int sidx = (lrow + (j) * 32) * STR_U32 + (kq >> 1);           \
        uint32_t h0, h1, l0, l1;                                            \
        split2((v).x, (v).y, h0, l0);                                       \
        split2((v).z, (v).w, h1, l1);                                       \
        *reinterpret_cast<uint2*>(&sAh[sidx]) = make_uint2(h0, h1);         \
        *reinterpret_cast<uint2*>(&sAl[sidx]) = make_uint2(l0, l1);         \
    }
#define SPLIT_STORE_B(v, j)                                                 \
    {                                                                       \
        const int sidx = (lrow + (j) * 32) * STR_U32 + (kq >> 1);           \
        uint32_t h0, h1, l0, l1;                                            \
        split2((v).x, (v).y, h0, l0);                                       \
        split2((v).z, (v).w, h1, l1);                                       \
        *reinterpret_cast<uint2*>(&sBh[sidx]) = make_uint2(h0, h1);         \
        *reinterpret_cast<uint2*>(&sBl[sidx]) = make_uint2(l0, l1);         \
    }

// ldmatrix + 3-term mma over one 32-k chunk in smem
#define MMA_CHUNK(acc)                                                      \
    _Pragma("unroll")                                                       \
    for (int ks = 0; ks < 2; ks++) {                                        \
        uint32_t Ah[4][4], Al[4][4], Bh[2][4], Bl[2][4];                    \
        _Pragma("unroll")                                                   \
        for (int mt = 0; mt < 4; mt++) {                                    \
            ldsm4(Ah[mt], SAh + aoff + mt * 16 * STR_B + ks * 32);          \
            ldsm4(Al[mt], SAl + aoff + mt * 16 * STR_B + ks * 32);          \
        }                                                                   \
        _Pragma("unroll")                                                   \
        for (int np = 0; np < 2; np++) {                                    \
            ldsm4(Bh[np], SBh + boff + np * 16 * STR_B + ks * 32);          \
            ldsm4(Bl[np], SBl + boff + np * 16 * STR_B + ks * 32);          \
        }                                                                   \
        _Pragma("unroll")                                                   \
        for (int mt = 0; mt < 4; mt++)                                      \
            _Pragma("unroll")                                               \
            for (int nt = 0; nt < 4; nt++) {                                \
                const uint32_t* bh = &Bh[nt >> 1][(nt & 1) * 2];            \
                const uint32_t* bl = &Bl[nt >> 1][(nt & 1) * 2];            \
                mma_bf16(acc[mt][nt], Ah[mt], bh);                          \
                mma_bf16(acc[mt][nt], Ah[mt], bl);                          \
                mma_bf16(acc[mt][nt], Al[mt], bh);                          \
            }                                                               \
    }

// ===========================================================================
// bf16-split-3 mma.sync GEMM (projections): Out = A x Bt^T (+bias)*scale
// ===========================================================================
__device__ __forceinline__ void mma_gemm(const float* __restrict__ A,
                                         const float* __restrict__ Bt,
                                         const float* __restrict__ bias,
                                         float* __restrict__ Out,
                                         float scale, int m0, int n0)
{
    __shared__ __align__(16) uint32_t sAh[128 * STR_U32];
    __shared__ __align__(16) uint32_t sAl[128 * STR_U32];
    __shared__ __align__(16) uint32_t sBh[128 * STR_U32];
    __shared__ __align__(16) uint32_t sBl[128 * STR_U32];

    MMA_IDX
    const uint32_t SAh = smem_u32(sAh), SAl = smem_u32(sAl);
    const uint32_t SBh = smem_u32(sBh), SBl = smem_u32(sBl);

    const float* pA = A + (size_t)(m0 + lrow) * Dd + kq;
    const float* pB = Bt + (size_t)(n0 + lrow) * Dd + kq;

    float acc[4][4][4];
#pragma unroll
    for (int mt = 0; mt < 4; mt++)
#pragma unroll
        for (int nt = 0; nt < 4; nt++)
#pragma unroll
            for (int q = 0; q < 4; q++) acc[mt][nt][q] = 0.f;

#pragma unroll 1
    for (int c = 0; c < 64; c++) {
        float4 va[4], vb[4];
#pragma unroll
        for (int j = 0; j < 4; j++) {
            va[j] = *reinterpret_cast<const float4*>(pA + (size_t)j * 32 * Dd + c * 32);
            vb[j] = *reinterpret_cast<const float4*>(pB + (size_t)j * 32 * Dd + c * 32);
        }
        __syncthreads();
#pragma unroll
        for (int j = 0; j < 4; j++) {
            SPLIT_STORE_A(va[j], j)
            SPLIT_STORE_B(vb[j], j)
        }
        __syncthreads();
        MMA_CHUNK(acc)
    }

    const int g = l >> 2, tg = l & 3;
#pragma unroll
    for (int mt = 0; mt < 4; mt++) {
        const int r0 = m0 + m_off + mt * 16 + g;
#pragma unroll
        for (int nt = 0; nt < 4; nt++) {
            const int col = n0 + n_off + nt * 8 + tg * 2;
            const float b0v = bias[col], b1v = bias[col + 1];
            *reinterpret_cast<float2*>(Out + (size_t)r0 * Dd + col) =
                make_float2((acc[mt][nt][0] + b0v) * scale, (acc[mt][nt][1] + b1v) * scale);
            *reinterpret_cast<float2*>(Out + (size_t)(r0 + 8) * Dd + col) =
                make_float2((acc[mt][nt][2] + b0v) * scale, (acc[mt][nt][3] + b1v) * scale);
        }
    }
}

__global__ __launch_bounds__(256)
void mma_proj_kernel(const float* __restrict__ X, const float* __restrict__ bq,
                     const float* __restrict__ bk, const float* __restrict__ bv)
{
    const int z = blockIdx.z;
    const float* Bt = g_wt + (size_t)z * Dd * Dd;
    const float* bias = (z == 0) ? bq : (z == 1) ? bk : bv;
    float* Out = (z == 0) ? g_q : (z == 1) ? g_k : g_v;
    const float scale = (z == 0) ? QSCALE : 1.0f;
    mma_gemm(X, Bt, bias, Out, scale, blockIdx.y * 128, blockIdx.x * 128);
}

__global__ __launch_bounds__(256)
void mma_oproj_kernel(const float* __restrict__ Wo, const float* __restrict__ ob,
                      float* __restrict__ out)
{
    mma_gemm(g_ctx, Wo, ob, out, 1.0f, blockIdx.y * 128, blockIdx.x * 128);
}

// ===========================================================================
// Logits: probs_raw = Q K^T + bias, with online per-row (max, sumexp) stats.
// A = Q[t][h], B = K[s][h], K-dim = Hd = 128 (4 chunks).
// ===========================================================================
__global__ __launch_bounds__(256)
void mma_logits_kernel(const float* __restrict__ biasTS, float* __restrict__ probs)
{
    __shared__ __align__(16) uint32_t sAh[128 * STR_U32];
    __shared__ __align__(16) uint32_t sAl[128 * STR_U32];
    __shared__ __align__(16) uint32_t sBh[128 * STR_U32];
    __shared__ __align__(16) uint32_t sBl[128 * STR_U32];
    __shared__ float red_m[128][4];
    __shared__ float red_s[128][4];

    const int bn = blockIdx.y;
    const int b = bn >> 4;
    const int n = bn & 15;
    const int t0 = blockIdx.x * 128;

    const float* __restrict__ Qp = g_q + (size_t)b * Tt * Dd + n * Hd;
    const float* __restrict__ Kp = g_k + (size_t)b * Tt * Dd + n * Hd;
    float* __restrict__ Lout = probs + (size_t)bn * Tt * Ss;

    MMA_IDX
    const uint32_t SAh = smem_u32(sAh), SAl = smem_u32(sAl);
    const uint32_t SBh = smem_u32(sBh), SBl = smem_u32(sBl);
    const int g = l >> 2, tg = l & 3;

    float mrun[4][2], srun[4][2];
#pragma unroll
    for (int mt = 0; mt < 4; mt++) {
        mrun[mt][0] = mrun[mt][1] = -1e30f;
        srun[mt][0] = srun[mt][1] = 0.f;
    }

#pragma unroll 1
    for (int st = 0; st < 16; st++) {
        const int s0 = st * 128;
        float acc[4][4][4];
#pragma unroll
        for (int mt = 0; mt < 4; mt++)
#pragma unroll
            for (int nt = 0; nt < 4; nt++)
#pragma unroll
                for (int q = 0; q < 4; q++) acc[mt][nt][q] = 0.f;

#pragma unroll 1
        for (int kc = 0; kc < 4; kc++) {
            float4 va[4], vb[4];
#pragma unroll
            for (int j = 0; j < 4; j++) {
                va[j] = *reinterpret_cast<const float4*>(
                    Qp + (size_t)(t0 + lrow + j * 32) * Dd + kc * 32 + kq);
                vb[j] = *reinterpret_cast<const float4*>(
                    Kp + (size_t)(s0 + lrow + j * 32) * Dd + kc * 32 + kq);
            }
            __syncthreads();
#pragma unroll
            for (int j = 0; j < 4; j++) {
                SPLIT_STORE_A(va[j], j)
                SPLIT_STORE_B(vb[j], j)
            }
            __syncthreads();
            MMA_CHUNK(acc)
        }

        // Epilogue: bias add, raw-logit store, running row stats
#pragma unroll
        for (int mt = 0; mt < 4; mt++) {
            const int r1 = t0 + m_off + mt * 16 + g;
            const int r2 = r1 + 8;
            float v1[8], v2[8];
#pragma unroll
            for (int nt = 0; nt < 4; nt++) {
                const int col = s0 + n_off + nt * 8 + tg * 2;
                float2 c1 = *reinterpret_cast<const float2*>(biasTS + (size_t)r1 * Ss + col);
                float2 c2 = *reinterpret_cast<const float2*>(biasTS + (size_t)r2 * Ss + col);
                v1[nt * 2 + 0] = acc[mt][nt][0] + c1.x;
                v1[nt * 2 + 1] = acc[mt][nt][1] + c1.y;
                v2[nt * 2 + 0] = acc[mt][nt][2] + c2.x;
                v2[nt * 2 + 1] = acc[mt][nt][3] + c2.y;
                *reinterpret_cast<float2*>(Lout + (size_t)r1 * Ss + col) =
                    make_float2(v1[nt * 2], v1[nt * 2 + 1]);
                *reinterpret_cast<float2*>(Lout + (size_t)r2 * Ss + col) =
                    make_float2(v2[nt * 2], v2[nt * 2 + 1]);
            }
            float tm1 = v1[0], tm2 = v2[0];
#pragma unroll
            for (int q = 1; q < 8; q++) { tm1 = fmaxf(tm1, v1[q]); tm2 = fmaxf(tm2, v2[q]); }
            float mn1 = fmaxf(mrun[mt][0], tm1);
            float mn2 = fmaxf(mrun[mt][1], tm2);
            float a1 = 0.f, a2 = 0.f;
#pragma unroll
            for (int q = 0; q < 8; q++) {
                a1 += __expf(v1[q] - mn1);
                a2 += __expf(v2[q] - mn2);
            }
            srun[mt][0] = srun[mt][0] * __expf(mrun[mt][0] - mn1) + a1;
            srun[mt][1] = srun[mt][1] * __expf(mrun[mt][1] - mn2) + a2;
            mrun[mt][0] = mn1;
            mrun[mt][1] = mn2;
        }
    }

    // Reduce over the 4 lanes (tg) sharing each row, then across the 4 n-warps
#pragma unroll
    for (int mt = 0; mt < 4; mt++)
#pragma unroll
        for (int i = 0; i < 2; i++) {
            float m = mrun[mt][i], s = srun[mt][i];
#pragma unroll
            for (int o = 1; o <= 2; o <<= 1) {
                float mo = __shfl_xor_sync(0xffffffffu, m, o);
                float so = __shfl_xor_sync(0xffffffffu, s, o);
                float mn = fmaxf(m, mo);
                s = s * __expf(m - mn) + so * __expf(mo - mn);
                m = mn;
            }
            if (tg == 0) {
                const int rl = m_off + mt * 16 + g + i * 8;
                red_m[rl][wid >> 1] = m;
                red_s[rl][wid >> 1] = s;
            }
        }
    __syncthreads();
    if (tid < 128) {
        float m = red_m[tid][0], s = red_s[tid][0];
#pragma unroll
        for (int x = 1; x < 4; x++) {
            float mo = red_m[tid][x], so = red_s[tid][x];
            float mn = fmaxf(m, mo);
            s = s * __expf(m - mn) + so * __expf(mo - mn);
            m = mn;
        }
        g_m[(size_t)bn * Tt + t0 + tid] = m;
        g_l[(size_t)bn * Tt + t0 + tid] = s;
    }
}

// ===========================================================================
// Softmax (in-place on probs) + PV -> g_ctx.  A = P[t][s], B = Vt[h][s].
// ===========================================================================
__global__ __launch_bounds__(256)
void mma_pv_kernel(float* __restrict__ probs)
{
    __shared__ __align__(16) uint32_t sAh[128 * STR_U32];
    __shared__ __align__(16) uint32_t sAl[128 * STR_U32];
    __shared__ __align__(16) uint32_t sBh[128 * STR_U32];
    __shared__ __align__(16) uint32_t sBl[128 * STR_U32];
    __shared__ float sm_m[128];
    __shared__ float sm_inv[128];

    const int bn = blockIdx.y;
    const int b = bn >> 4;
    const int n = bn & 15;
    const int t0 = blockIdx.x * 128;

    float* __restrict__ Lp = probs + (size_t)bn * Tt * Ss;
    const float* __restrict__ Vt = g_vt + (size_t)bn * Hd * Tt;

    MMA_IDX
    const uint32_t SAh = smem_u32(sAh), SAl = smem_u32(sAl);
    const uint32_t SBh = smem_u32(sBh), SBl = smem_u32(sBl);

    if (tid < 128) {
        sm_m[tid] = g_m[(size_t)bn * Tt + t0 + tid];
        sm_inv[tid] = 1.0f / g_l[(size_t)bn * Tt + t0 + tid];
    }
    __syncthreads();

    float acc[4][4][4];
#pragma unroll
    for (int mt = 0; mt < 4; mt++)
#pragma unroll
        for (int nt = 0; nt < 4; nt++)
#pragma unroll
            for (int q = 0; q < 4; q++) acc[mt][nt][q] = 0.f;

#pragma unroll 1
    for (int c = 0; c < 64; c++) {
        float4 va[4], vb[4];
#pragma unroll
        for (int j = 0; j < 4; j++) {
            const int row = lrow + j * 32;
            float4 pv = *reinterpret_cast<const float4*>(
                Lp + (size_t)(t0 + row) * Ss + c * 32 + kq);
            const float mm = sm_m[row], iv = sm_inv[row];
            pv.x = __expf(pv.x - mm) * iv;
            pv.y = __expf(pv.y - mm) * iv;
            pv.z = __expf(pv.z - mm) * iv;
            pv.w = __expf(pv.w - mm) * iv;
            *reinterpret_cast<float4*>(Lp + (size_t)(t0 + row) * Ss + c * 32 + kq) = pv;
            va[j] = pv;
            vb[j] = *reinterpret_cast<const float4*>(
                Vt + (size_t)row * Tt + c * 32 + kq);
        }
        __syncthreads();
#pragma unroll
        for (int j = 0; j < 4; j++) {
            SPLIT_STORE_A(va[j], j)
            SPLIT_STORE_B(vb[j], j)
        }
        __syncthreads();
        MMA_CHUNK(acc)
    }

    const int g = l >> 2, tg = l & 3;
#pragma unroll
    for (int mt = 0; mt < 4; mt++) {
        const int r0 = t0 + m_off + mt * 16 + g;
#pragma unroll
        for (int nt = 0; nt < 4; nt++) {
            const int col = n_off + nt * 8 + tg * 2;
            float* c1 = g_ctx + (size_t)(b * Tt + r0) * Dd + n * Hd + col;
            float* c2 = g_ctx + (size_t)(b * Tt + r0 + 8) * Dd + n * Hd + col;
            *reinterpret_cast<float2*>(c1) = make_float2(acc[mt][nt][0], acc[mt][nt][1]);
            *reinterpret_cast<float2*>(c2) = make_float2(acc[mt][nt][2], acc[mt][nt][3]);
        }
    }
}

// ===========================================================================
// One-time transposes
// ===========================================================================
__global__ void transpose_w_kernel(const float* __restrict__ Wq,
                                   const float* __restrict__ Wk,
                                   const float* __restrict__ Wv)
{
    __shared__ float ts[32][33];
    const int z = blockIdx.z;
    const float* W = (z == 0) ? Wq : (z == 1) ? Wk : Wv;
    float* Wt = g_wt + (size_t)z * Dd * Dd;
    const int bx = blockIdx.x * 32, by = blockIdx.y * 32;
    const int tx = threadIdx.x, ty = threadIdx.y;
#pragma unroll
    for (int r = 0; r < 32; r += 8)
        ts[ty + r][tx] = W[(size_t)(by + ty + r) * Dd + bx + tx];
    __syncthreads();
#pragma unroll
    for (int r = 0; r < 32; r += 8)
        Wt[(size_t)(bx + ty + r) * Dd + by + tx] = ts[tx][ty + r];
}

// g_vt[bn][h][s] = g_v[b][s][n*128+h]
__global__ void transpose_v_kernel()
{
    __shared__ float ts[32][33];
    const int bn = blockIdx.z;
    const int b = bn >> 4;
    const int n = bn & 15;
    const int s0 = blockIdx.x * 32, h0 = blockIdx.y * 32;
    const int tx = threadIdx.x, ty = threadIdx.y;
#pragma unroll
    for (int r = 0; r < 32; r += 8)
        ts[ty + r][tx] = g_v[(size_t)(b * Tt + s0 + ty + r) * Dd + n * Hd + h0 + tx];
    __syncthreads();
#pragma unroll
    for (int r = 0; r < 32; r += 8)
        g_vt[((size_t)bn * Hd + h0 + ty + r) * Tt + s0 + tx] = ts[tx][ty + r];
}

// ===========================================================================
extern "C" void kernel_launch(void* const* d_in, const int* in_sizes, int n_in,
                              void* d_out, int out_size)
{
    const float* query  = (const float*)d_in[0];
    const float* biasTS = (const float*)d_in[1];
    const float* wq = (const float*)d_in[2];
    const float* bq = (const float*)d_in[3];
    const float* wk = (const float*)d_in[4];
    const float* bk = (const float*)d_in[5];
    const float* wv = (const float*)d_in[6];
    const float* bv = (const float*)d_in[7];
    const float* wo = (const float*)d_in[8];
    const float* obias = (const float*)d_in[9];

    float* data_out  = (float*)d_out;
    float* probs_out = data_out + (size_t)Bb * Tt * Dd;

    transpose_w_kernel<<<dim3(Dd / 32, Dd / 32, 3), dim3(32, 8)>>>(wq, wk, wv);
    mma_proj_kernel<<<dim3(Dd / 128, (Bb * Tt) / 128, 3), 256>>>(query, bq, bk, bv);
    transpose_v_kernel<<<dim3(Tt / 32, Hd / 32, Bb * Nh), dim3(32, 8)>>>();
    mma_logits_kernel<<<dim3(Tt / 128, Bb * Nh), 256>>>(biasTS, probs_out);
    mma_pv_kernel<<<dim3(Tt / 128, Bb * Nh), 256>>>(probs_out);
    mma_oproj_kernel<<<dim3(Dd / 128, (Bb * Tt) / 128), 256>>>(wo, obias, data_out);
}